// round 2
// baseline (speedup 1.0000x reference)
#include <cuda_runtime.h>

//
// Morphological skeleton, merged erode+dilate single-pass-per-iteration kernel.
//
// skel = sum_{j=0..20} ( x_j - dilate3(x_{j+1}) ),  x_{j+1} = erode3(x_j)
//
// Pass p (reading buffer holding x_p):
//   - rowmin/rowmax of each row computed ONCE from one LDS.128 (+shuffles)
//   - vertical min -> x_{p+1} written to other buffer (which held x_{p-1})
//   - vertical max -> dilate(x_p); acc += x_{p-1} - dilate  (x_{p-1} read from
//     the other buffer just before the same thread overwrites that cell)
// Launch 1: K=11 erosions (passes 0..11), writes x_11 to scratch, skel init.
// Launch 2: K=10 erosions (passes 0..10), accumulates skel.
//

#define IMG    1024
#define NIMG   16
#define TILE   128
#define HALO   12
#define RW     152                 /* region valid width/height   */
#define RWP    160                 /* padded row stride (floats)  */
#define NT     640                 /* 40 cols x 16 strips         */
#define NCOL   40
#define RPS    10                  /* rows per strip              */
#define SMEMB  (2 * RW * RWP * 4)  /* 194560 bytes                */

__device__ float g_scratch[(size_t)NIMG * IMG * IMG];

__device__ __forceinline__ float min3f(float a, float b, float c) { return fminf(fminf(a, b), c); }
__device__ __forceinline__ float max3f(float a, float b, float c) { return fmaxf(fmaxf(a, b), c); }

// load one row-block, produce horizontal 3-min and 3-max using shuffles
__device__ __forceinline__ void rowmm(const float* __restrict__ row, int xb, int lane, int c,
                                      float4& mn, float4& mx)
{
    float4 v = *(const float4*)(row + xb);
    float l = __shfl_up_sync(0xffffffffu, v.w, 1);
    float r = __shfl_down_sync(0xffffffffu, v.x, 1);
    if (lane == 0 || c == 0)
        l = (xb > 0) ? row[xb - 1] : v.x;          // region-edge replicate (min-safe)
    if (lane == 31 || c >= 37)
        r = (xb + 4 < RW) ? row[xb + 4] : v.w;
    mn.x = min3f(l,   v.x, v.y);
    mn.y = min3f(v.x, v.y, v.z);
    mn.z = min3f(v.y, v.z, v.w);
    mn.w = min3f(v.z, v.w, r);
    mx.x = max3f(l,   v.x, v.y);
    mx.y = max3f(v.x, v.y, v.z);
    mx.z = max3f(v.y, v.z, v.w);
    mx.w = max3f(v.z, v.w, r);
}

__global__ void __launch_bounds__(NT, 1)
skel_merged_kernel(const float* __restrict__ xin,
                   float* __restrict__ xout,
                   float* __restrict__ skel,
                   int K, int accum, int writex)
{
    extern __shared__ float smem[];
    float* cur = smem;             // x_p
    float* nxt = smem + RW * RWP;  // x_{p-1}, becomes x_{p+1}

    const int tid  = threadIdx.x;
    const int lane = tid & 31;
    const int bx = blockIdx.x, by = blockIdx.y, bz = blockIdx.z;
    const int gx0 = bx * TILE - HALO;
    const int gy0 = by * TILE - HALO;
    const float* img = xin + (size_t)bz * IMG * IMG;

    // ---- load region with replicate clamp ----
    for (int i = tid; i < RW * RW; i += NT) {
        int y = i / RW;
        int x = i - y * RW;
        int gy = min(max(gy0 + y, 0), IMG - 1);
        int gx = min(max(gx0 + x, 0), IMG - 1);
        cur[y * RWP + x] = img[(size_t)gy * IMG + gx];
    }
    __syncthreads();

    const bool topE   = (by == 0);
    const bool botE   = (by == (int)gridDim.y - 1);
    const bool leftE  = (bx == 0);
    const bool rightE = (bx == (int)gridDim.x - 1);
    const bool anyE   = topE || botE || leftE || rightE;

    const int c  = tid % NCOL;                   // float4 column 0..39
    const int s  = tid / NCOL;                   // strip 0..15
    const int xb = min(c * 4, RW - 4);           // clamp loads for c=38,39
    const bool colA = (c <= 37);                 // column computes erode
    const bool dcol = (xb >= HALO) && (xb + 4 <= HALO + TILE);  // interior col block
    const int y0 = s * RPS;

    float4 acc[RPS];
#pragma unroll
    for (int k = 0; k < RPS; k++) acc[k] = make_float4(0.f, 0.f, 0.f, 0.f);

    for (int p = 0; p <= K; ++p) {
        const bool doE = (p < K);
        const bool doD = (p > 0);
        const int  m   = K - p;                         // erode output margin
        const int  elo = doE ? (HALO - m) : HALO;
        const int  ehi = doE ? (HALO + TILE + m) : (HALO + TILE);

        // prime rolling ring with rows y0-1, y0 (clamped; polluted rows are pred-off)
        float4 amn, amx, bmn, bmx;
        rowmm(cur + max(y0 - 1, 0) * RWP, xb, lane, c, amn, amx);
        rowmm(cur + y0 * RWP,             xb, lane, c, bmn, bmx);

#pragma unroll
        for (int k = 0; k < RPS; k++) {
            const int y = y0 + k;
            float4 cmn, cmx;
            rowmm(cur + min(y + 1, RW - 1) * RWP, xb, lane, c, cmn, cmx);

            // dilate(x_p) + accumulate (reads nxt BEFORE erode store overwrites it)
            if (doD && dcol && y >= HALO && y < HALO + TILE) {
                float4 xv = *(const float4*)(nxt + y * RWP + xb);
                acc[k].x += xv.x - max3f(amx.x, bmx.x, cmx.x);
                acc[k].y += xv.y - max3f(amx.y, bmx.y, cmx.y);
                acc[k].z += xv.z - max3f(amx.z, bmx.z, cmx.z);
                acc[k].w += xv.w - max3f(amx.w, bmx.w, cmx.w);
            }
            // erode -> x_{p+1}
            if (doE && colA && y >= elo && y < ehi) {
                float4 e;
                e.x = min3f(amn.x, bmn.x, cmn.x);
                e.y = min3f(amn.y, bmn.y, cmn.y);
                e.z = min3f(amn.z, bmn.z, cmn.z);
                e.w = min3f(amn.w, bmn.w, cmn.w);
                *(float4*)(nxt + y * RWP + xb) = e;
            }
            amn = bmn; amx = bmx; bmn = cmn; bmx = cmx;
        }
        __syncthreads();

        // image-border ring fix-up on the freshly eroded buffer (edge blocks)
        if (doE && anyE) {
            if (tid < TILE + 2) {
                int o = HALO - 1 + tid;                    // 11..140
                int sx = o;
                if (leftE  && sx < HALO)             sx = HALO;
                if (rightE && sx > HALO + TILE - 1)  sx = HALO + TILE - 1;
                int sy = o;
                if (topE && sy < HALO)               sy = HALO;
                if (botE && sy > HALO + TILE - 1)    sy = HALO + TILE - 1;
                if (topE)   nxt[(HALO - 1) * RWP + o]      = nxt[HALO * RWP + sx];
                if (botE)   nxt[(HALO + TILE) * RWP + o]   = nxt[(HALO + TILE - 1) * RWP + sx];
                if (leftE)  nxt[o * RWP + (HALO - 1)]      = nxt[sy * RWP + HALO];
                if (rightE) nxt[o * RWP + (HALO + TILE)]   = nxt[sy * RWP + (HALO + TILE - 1)];
            }
            __syncthreads();
        }

        if (doE) { float* t = cur; cur = nxt; nxt = t; }
    }

    // ---- outputs: skel (+= or =) and optionally x_K ----
    if (dcol) {
        float* so = skel + (size_t)bz * IMG * IMG;
        float* xo = xout + (size_t)bz * IMG * IMG;
#pragma unroll
        for (int k = 0; k < RPS; k++) {
            const int y = y0 + k;
            if (y >= HALO && y < HALO + TILE) {
                const size_t off = (size_t)(by * TILE + (y - HALO)) * IMG
                                 + (size_t)(bx * TILE + (xb - HALO));
                if (writex)
                    *(float4*)(xo + off) = *(const float4*)(cur + y * RWP + xb);
                if (accum) {
                    float4 sv = *(const float4*)(so + off);
                    sv.x += acc[k].x; sv.y += acc[k].y;
                    sv.z += acc[k].z; sv.w += acc[k].w;
                    *(float4*)(so + off) = sv;
                } else {
                    *(float4*)(so + off) = acc[k];
                }
            }
        }
    }
}

extern "C" void kernel_launch(void* const* d_in, const int* in_sizes, int n_in,
                              void* d_out, int out_size)
{
    (void)in_sizes; (void)n_in; (void)out_size;
    const float* x = (const float*)d_in[0];
    float* skel = (float*)d_out;

    float* scratch = nullptr;
    cudaGetSymbolAddress((void**)&scratch, g_scratch);

    cudaFuncSetAttribute(skel_merged_kernel,
                         cudaFuncAttributeMaxDynamicSharedMemorySize, SMEMB);

    dim3 grid(IMG / TILE, IMG / TILE, NIMG);   // 8 x 8 x 16
    // iterations 0..10 (11 terms): init skel, write x_11 to scratch
    skel_merged_kernel<<<grid, NT, SMEMB>>>(x, scratch, skel, 11, 0, 1);
    // iterations 11..20 (10 terms): accumulate skel
    skel_merged_kernel<<<grid, NT, SMEMB>>>(scratch, scratch, skel, 10, 1, 0);
}

// round 3
// speedup vs baseline: 1.0023x; 1.0023x over previous
#include <cuda_runtime.h>

//
// Morphological skeleton, merged erode+dilate single-pass-per-iteration kernel.
//
// skel = sum_{j=0..20} ( x_j - dilate3(x_{j+1}) ),  x_{j+1} = erode3(x_j)
//
// Pass p (reading buffer holding x_p):
//   - rowmin/rowmax of each row computed ONCE from one LDS.128 (+shuffles)
//   - vertical min -> x_{p+1} written to other buffer (which held x_{p-1})
//   - vertical max -> dilate(x_p); acc += x_{p-1} - dilate  (x_{p-1} read from
//     the other buffer just before the same thread overwrites that cell)
// Launch 1: K=11 erosions (passes 0..11), writes x_11 to scratch, skel init.
// Launch 2: K=10 erosions (passes 0..10), accumulates skel.
//

#define IMG    1024
#define NIMG   16
#define TILE   128
#define HALO   12
#define RW     152                 /* region valid width/height   */
#define RWP    160                 /* padded row stride (floats)  */
#define NT     640                 /* 40 cols x 16 strips         */
#define NCOL   40
#define RPS    10                  /* rows per strip              */
#define SMEMB  (2 * RW * RWP * 4)  /* 194560 bytes                */

__device__ float g_scratch[(size_t)NIMG * IMG * IMG];

__device__ __forceinline__ float min3f(float a, float b, float c) { return fminf(fminf(a, b), c); }
__device__ __forceinline__ float max3f(float a, float b, float c) { return fmaxf(fmaxf(a, b), c); }

// load one row-block, produce horizontal 3-min and 3-max using shuffles
__device__ __forceinline__ void rowmm(const float* __restrict__ row, int xb, int lane, int c,
                                      float4& mn, float4& mx)
{
    float4 v = *(const float4*)(row + xb);
    float l = __shfl_up_sync(0xffffffffu, v.w, 1);
    float r = __shfl_down_sync(0xffffffffu, v.x, 1);
    if (lane == 0 || c == 0)
        l = (xb > 0) ? row[xb - 1] : v.x;          // region-edge replicate (min-safe)
    if (lane == 31 || c >= 37)
        r = (xb + 4 < RW) ? row[xb + 4] : v.w;
    mn.x = min3f(l,   v.x, v.y);
    mn.y = min3f(v.x, v.y, v.z);
    mn.z = min3f(v.y, v.z, v.w);
    mn.w = min3f(v.z, v.w, r);
    mx.x = max3f(l,   v.x, v.y);
    mx.y = max3f(v.x, v.y, v.z);
    mx.z = max3f(v.y, v.z, v.w);
    mx.w = max3f(v.z, v.w, r);
}

__global__ void __launch_bounds__(NT, 1)
skel_merged_kernel(const float* __restrict__ xin,
                   float* __restrict__ xout,
                   float* __restrict__ skel,
                   int K, int accum, int writex)
{
    extern __shared__ float smem[];
    float* cur = smem;             // x_p
    float* nxt = smem + RW * RWP;  // x_{p-1}, becomes x_{p+1}

    const int tid  = threadIdx.x;
    const int lane = tid & 31;
    const int bx = blockIdx.x, by = blockIdx.y, bz = blockIdx.z;
    const int gx0 = bx * TILE - HALO;
    const int gy0 = by * TILE - HALO;
    const float* img = xin + (size_t)bz * IMG * IMG;

    // ---- load region with replicate clamp ----
    for (int i = tid; i < RW * RW; i += NT) {
        int y = i / RW;
        int x = i - y * RW;
        int gy = min(max(gy0 + y, 0), IMG - 1);
        int gx = min(max(gx0 + x, 0), IMG - 1);
        cur[y * RWP + x] = img[(size_t)gy * IMG + gx];
    }
    __syncthreads();

    const bool topE   = (by == 0);
    const bool botE   = (by == (int)gridDim.y - 1);
    const bool leftE  = (bx == 0);
    const bool rightE = (bx == (int)gridDim.x - 1);
    const bool anyE   = topE || botE || leftE || rightE;

    const int c  = tid % NCOL;                   // float4 column 0..39
    const int s  = tid / NCOL;                   // strip 0..15
    const int xb = min(c * 4, RW - 4);           // clamp loads for c=38,39
    const bool colA = (c <= 37);                 // column computes erode
    const bool dcol = (xb >= HALO) && (xb + 4 <= HALO + TILE);  // interior col block
    const int y0 = s * RPS;

    float4 acc[RPS];
#pragma unroll
    for (int k = 0; k < RPS; k++) acc[k] = make_float4(0.f, 0.f, 0.f, 0.f);

    for (int p = 0; p <= K; ++p) {
        const bool doE = (p < K);
        const bool doD = (p > 0);
        const int  m   = K - p;                         // erode output margin
        const int  elo = doE ? (HALO - m) : HALO;
        const int  ehi = doE ? (HALO + TILE + m) : (HALO + TILE);

        // prime rolling ring with rows y0-1, y0 (clamped; polluted rows are pred-off)
        float4 amn, amx, bmn, bmx;
        rowmm(cur + max(y0 - 1, 0) * RWP, xb, lane, c, amn, amx);
        rowmm(cur + y0 * RWP,             xb, lane, c, bmn, bmx);

#pragma unroll
        for (int k = 0; k < RPS; k++) {
            const int y = y0 + k;
            float4 cmn, cmx;
            rowmm(cur + min(y + 1, RW - 1) * RWP, xb, lane, c, cmn, cmx);

            // dilate(x_p) + accumulate (reads nxt BEFORE erode store overwrites it)
            if (doD && dcol && y >= HALO && y < HALO + TILE) {
                float4 xv = *(const float4*)(nxt + y * RWP + xb);
                acc[k].x += xv.x - max3f(amx.x, bmx.x, cmx.x);
                acc[k].y += xv.y - max3f(amx.y, bmx.y, cmx.y);
                acc[k].z += xv.z - max3f(amx.z, bmx.z, cmx.z);
                acc[k].w += xv.w - max3f(amx.w, bmx.w, cmx.w);
            }
            // erode -> x_{p+1}
            if (doE && colA && y >= elo && y < ehi) {
                float4 e;
                e.x = min3f(amn.x, bmn.x, cmn.x);
                e.y = min3f(amn.y, bmn.y, cmn.y);
                e.z = min3f(amn.z, bmn.z, cmn.z);
                e.w = min3f(amn.w, bmn.w, cmn.w);
                *(float4*)(nxt + y * RWP + xb) = e;
            }
            amn = bmn; amx = bmx; bmn = cmn; bmx = cmx;
        }
        __syncthreads();

        // image-border ring fix-up on the freshly eroded buffer (edge blocks)
        if (doE && anyE) {
            if (tid < TILE + 2) {
                int o = HALO - 1 + tid;                    // 11..140
                int sx = o;
                if (leftE  && sx < HALO)             sx = HALO;
                if (rightE && sx > HALO + TILE - 1)  sx = HALO + TILE - 1;
                int sy = o;
                if (topE && sy < HALO)               sy = HALO;
                if (botE && sy > HALO + TILE - 1)    sy = HALO + TILE - 1;
                if (topE)   nxt[(HALO - 1) * RWP + o]      = nxt[HALO * RWP + sx];
                if (botE)   nxt[(HALO + TILE) * RWP + o]   = nxt[(HALO + TILE - 1) * RWP + sx];
                if (leftE)  nxt[o * RWP + (HALO - 1)]      = nxt[sy * RWP + HALO];
                if (rightE) nxt[o * RWP + (HALO + TILE)]   = nxt[sy * RWP + (HALO + TILE - 1)];
            }
            __syncthreads();
        }

        if (doE) { float* t = cur; cur = nxt; nxt = t; }
    }

    // ---- outputs: skel (+= or =) and optionally x_K ----
    if (dcol) {
        float* so = skel + (size_t)bz * IMG * IMG;
        float* xo = xout + (size_t)bz * IMG * IMG;
#pragma unroll
        for (int k = 0; k < RPS; k++) {
            const int y = y0 + k;
            if (y >= HALO && y < HALO + TILE) {
                const size_t off = (size_t)(by * TILE + (y - HALO)) * IMG
                                 + (size_t)(bx * TILE + (xb - HALO));
                if (writex)
                    *(float4*)(xo + off) = *(const float4*)(cur + y * RWP + xb);
                if (accum) {
                    float4 sv = *(const float4*)(so + off);
                    sv.x += acc[k].x; sv.y += acc[k].y;
                    sv.z += acc[k].z; sv.w += acc[k].w;
                    *(float4*)(so + off) = sv;
                } else {
                    *(float4*)(so + off) = acc[k];
                }
            }
        }
    }
}

extern "C" void kernel_launch(void* const* d_in, const int* in_sizes, int n_in,
                              void* d_out, int out_size)
{
    (void)in_sizes; (void)n_in; (void)out_size;
    const float* x = (const float*)d_in[0];
    float* skel = (float*)d_out;

    float* scratch = nullptr;
    cudaGetSymbolAddress((void**)&scratch, g_scratch);

    cudaFuncSetAttribute(skel_merged_kernel,
                         cudaFuncAttributeMaxDynamicSharedMemorySize, SMEMB);

    dim3 grid(IMG / TILE, IMG / TILE, NIMG);   // 8 x 8 x 16
    // iterations 0..10 (11 terms): init skel, write x_11 to scratch
    skel_merged_kernel<<<grid, NT, SMEMB>>>(x, scratch, skel, 11, 0, 1);
    // iterations 11..20 (10 terms): accumulate skel
    skel_merged_kernel<<<grid, NT, SMEMB>>>(scratch, scratch, skel, 10, 1, 0);
}

// round 4
// speedup vs baseline: 1.2819x; 1.2790x over previous
#include <cuda_runtime.h>

//
// Morphological skeleton — merged erode+dilate, one smem pass per iteration.
//
// skel = sum_{j=0..20} ( x_j - dilate3(x_{j+1}) ),  x_{j+1} = erode3(x_j)
//
// Pass p (buffer cur = x_p, buffer nxt = x_{p-1}):
//   one LDS.128 + 2 scalar LDS per row-block -> horizontal 3-min AND 3-max
//   vertical min -> x_{p+1} stored into nxt (over x_{p-1}, same-thread RAW-safe)
//   vertical max -> dilate(x_p); acc += x_{p-1} - dilate (x_{p-1} read first)
// Launch 1: K=11, skel init, writes x_11 to scratch. Launch 2: K=10, accum.
//
// No shuffles: neighbor cells fetched with independent scalar LDS so all three
// row loads overlap (R2's shfl chain serialized the whole row pipeline).
//

#define IMG    1024
#define NIMG   16
#define TILE   128
#define HALO   12
#define RW     152                 /* region valid width/height   */
#define RWP    164                 /* padded row stride: 164%32=4 kills cross-strip bank aliasing */
#define NCOL   38                  /* float4 columns: exactly covers 152 */
#define NSTR   16
#define NT     (NCOL*NSTR)         /* 608 threads = 19 warps      */
#define RPS    10                  /* rows per strip (16*10=160 >= 152) */
#define SMEMB  (2 * RW * RWP * 4)  /* 199424 bytes                */

__device__ float g_scratch[(size_t)NIMG * IMG * IMG];

__device__ __forceinline__ float min3f(float a, float b, float c) { return fminf(fminf(a, b), c); }
__device__ __forceinline__ float max3f(float a, float b, float c) { return fmaxf(fmaxf(a, b), c); }

// One row-block: 1x LDS.128 + 2x independent scalar LDS -> h-min and h-max of 4 px
__device__ __forceinline__ void rowmm(const float* __restrict__ row, int xb,
                                      float4& mn, float4& mx)
{
    float4 v = *(const float4*)(row + xb);
    float l = (xb > 0)       ? row[xb - 1] : v.x;   // replicate at region edge (min-safe;
    float r = (xb + 4 < RW)  ? row[xb + 4] : v.w;   //  dilate never consumes edge columns)
    mn.x = min3f(l,   v.x, v.y);
    mn.y = min3f(v.x, v.y, v.z);
    mn.z = min3f(v.y, v.z, v.w);
    mn.w = min3f(v.z, v.w, r);
    mx.x = max3f(l,   v.x, v.y);
    mx.y = max3f(v.x, v.y, v.z);
    mx.z = max3f(v.y, v.z, v.w);
    mx.w = max3f(v.z, v.w, r);
}

__global__ void __launch_bounds__(NT, 1)
skel_merged_kernel(const float* __restrict__ xin,
                   float* __restrict__ xout,
                   float* __restrict__ skel,
                   int K, int accum, int writex)
{
    extern __shared__ float smem[];
    float* cur = smem;             // x_p
    float* nxt = smem + RW * RWP;  // x_{p-1} -> becomes x_{p+1}

    const int tid = threadIdx.x;
    const int bx = blockIdx.x, by = blockIdx.y, bz = blockIdx.z;
    const int gx0 = bx * TILE - HALO;
    const int gy0 = by * TILE - HALO;
    const float* img = xin + (size_t)bz * IMG * IMG;

    // ---- load region with replicate clamp ----
    for (int i = tid; i < RW * RW; i += NT) {
        int y = i / RW;
        int x = i - y * RW;
        int gy = min(max(gy0 + y, 0), IMG - 1);
        int gx = min(max(gx0 + x, 0), IMG - 1);
        cur[y * RWP + x] = img[(size_t)gy * IMG + gx];
    }
    __syncthreads();

    const bool topE   = (by == 0);
    const bool botE   = (by == (int)gridDim.y - 1);
    const bool leftE  = (bx == 0);
    const bool rightE = (bx == (int)gridDim.x - 1);
    const bool anyE   = topE || botE || leftE || rightE;

    const int c  = tid % NCOL;                   // float4 column 0..37
    const int s  = tid / NCOL;                   // strip 0..15
    const int xb = c * 4;                        // 0..148, always in-bounds
    const bool dcol = (xb >= HALO) && (xb + 4 <= HALO + TILE);  // interior col block
    const int y0 = s * RPS;

    float4 acc[RPS];
#pragma unroll
    for (int k = 0; k < RPS; k++) acc[k] = make_float4(0.f, 0.f, 0.f, 0.f);

    for (int p = 0; p <= K; ++p) {
        const bool doE = (p < K);
        const bool doD = (p > 0);
        const int  m   = K - p;                         // erode validity margin
        const int  elo = doE ? (HALO - m) : HALO;
        const int  ehi = doE ? (HALO + TILE + m) : (HALO + TILE);

        // prime the 3-row rolling ring (vertical replicate clamp; min-safe,
        // clamped rows never reach dilate's interior consumers)
        float4 amn, amx, bmn, bmx;
        rowmm(cur + max(y0 - 1, 0) * RWP, xb, amn, amx);
        rowmm(cur + y0 * RWP,             xb, bmn, bmx);

#pragma unroll
        for (int k = 0; k < RPS; k++) {
            const int y = y0 + k;
            float4 cmn, cmx;
            rowmm(cur + min(y + 1, RW - 1) * RWP, xb, cmn, cmx);

            // dilate(x_p) at interior; read x_{p-1} from nxt BEFORE overwriting
            if (doD && dcol && y >= HALO && y < HALO + TILE) {
                float4 xv = *(const float4*)(nxt + y * RWP + xb);
                acc[k].x += xv.x - max3f(amx.x, bmx.x, cmx.x);
                acc[k].y += xv.y - max3f(amx.y, bmx.y, cmx.y);
                acc[k].z += xv.z - max3f(amx.z, bmx.z, cmx.z);
                acc[k].w += xv.w - max3f(amx.w, bmx.w, cmx.w);
            }
            // erode -> x_{p+1}
            if (doE && y >= elo && y < ehi) {
                float4 e;
                e.x = min3f(amn.x, bmn.x, cmn.x);
                e.y = min3f(amn.y, bmn.y, cmn.y);
                e.z = min3f(amn.z, bmn.z, cmn.z);
                e.w = min3f(amn.w, bmn.w, cmn.w);
                *(float4*)(nxt + y * RWP + xb) = e;
            }
            amn = bmn; amx = bmx; bmn = cmn; bmx = cmx;
        }
        __syncthreads();

        // image-border ring fix-up on the freshly eroded buffer (edge blocks only)
        if (doE && anyE) {
            if (tid < TILE + 2) {
                int o = HALO - 1 + tid;                    // 11..140
                int sx = o;
                if (leftE  && sx < HALO)             sx = HALO;
                if (rightE && sx > HALO + TILE - 1)  sx = HALO + TILE - 1;
                int sy = o;
                if (topE && sy < HALO)               sy = HALO;
                if (botE && sy > HALO + TILE - 1)    sy = HALO + TILE - 1;
                if (topE)   nxt[(HALO - 1) * RWP + o]      = nxt[HALO * RWP + sx];
                if (botE)   nxt[(HALO + TILE) * RWP + o]   = nxt[(HALO + TILE - 1) * RWP + sx];
                if (leftE)  nxt[o * RWP + (HALO - 1)]      = nxt[sy * RWP + HALO];
                if (rightE) nxt[o * RWP + (HALO + TILE)]   = nxt[sy * RWP + (HALO + TILE - 1)];
            }
            __syncthreads();
        }

        if (doE) { float* t = cur; cur = nxt; nxt = t; }
    }

    // ---- outputs ----
    if (dcol) {
        float* so = skel + (size_t)bz * IMG * IMG;
        float* xo = xout + (size_t)bz * IMG * IMG;
#pragma unroll
        for (int k = 0; k < RPS; k++) {
            const int y = y0 + k;
            if (y >= HALO && y < HALO + TILE) {
                const size_t off = (size_t)(by * TILE + (y - HALO)) * IMG
                                 + (size_t)(bx * TILE + (xb - HALO));
                if (writex)
                    *(float4*)(xo + off) = *(const float4*)(cur + y * RWP + xb);
                if (accum) {
                    float4 sv = *(const float4*)(so + off);
                    sv.x += acc[k].x; sv.y += acc[k].y;
                    sv.z += acc[k].z; sv.w += acc[k].w;
                    *(float4*)(so + off) = sv;
                } else {
                    *(float4*)(so + off) = acc[k];
                }
            }
        }
    }
}

extern "C" void kernel_launch(void* const* d_in, const int* in_sizes, int n_in,
                              void* d_out, int out_size)
{
    (void)in_sizes; (void)n_in; (void)out_size;
    const float* x = (const float*)d_in[0];
    float* skel = (float*)d_out;

    float* scratch = nullptr;
    cudaGetSymbolAddress((void**)&scratch, g_scratch);

    cudaFuncSetAttribute(skel_merged_kernel,
                         cudaFuncAttributeMaxDynamicSharedMemorySize, SMEMB);

    dim3 grid(IMG / TILE, IMG / TILE, NIMG);   // 8 x 8 x 16
    // iterations 0..10 (11 terms): init skel, write x_11 to scratch
    skel_merged_kernel<<<grid, NT, SMEMB>>>(x, scratch, skel, 11, 0, 1);
    // iterations 11..20 (10 terms): accumulate skel
    skel_merged_kernel<<<grid, NT, SMEMB>>>(scratch, scratch, skel, 10, 1, 0);
}